// round 1
// baseline (speedup 1.0000x reference)
#include <cuda_runtime.h>

#define Bn 32
#define Nn 1024
#define Cn 768
#define NCHUNK 8
#define NPER   128   // Nn / NCHUNK

// Scratch (no allocation allowed in kernel_launch)
__device__ float g_part[NCHUNK * Bn * Cn];  // partial channel sums
__device__ float g_alpha[Bn * 4];           // per-batch merge coefficients

// Pass 1: partial sums over N, split 8 ways for SM occupancy.
// grid (Bn, 3, NCHUNK), block 256. Thread owns one channel c for 128 rows.
__global__ void pool_partial_kernel(const float* __restrict__ x) {
    int b = blockIdx.x;
    int c = blockIdx.y * 256 + threadIdx.x;
    int z = blockIdx.z;
    const float* p = x + ((size_t)b * Nn + (size_t)z * NPER) * Cn + c;
    float s0 = 0.f, s1 = 0.f, s2 = 0.f, s3 = 0.f;
#pragma unroll
    for (int n = 0; n < NPER; n += 4) {
        s0 += p[(size_t)(n + 0) * Cn];
        s1 += p[(size_t)(n + 1) * Cn];
        s2 += p[(size_t)(n + 2) * Cn];
        s3 += p[(size_t)(n + 3) * Cn];
    }
    g_part[((size_t)z * Bn + b) * Cn + c] = (s0 + s1) + (s2 + s3);
}

// Pass 2: alpha[b,k] = (1/1024) * sum_c sum_z part[z,b,c] * W[k,c] + bias[k]
// grid (Bn), block 768. Deterministic shared-memory tree reduction.
__global__ void alpha_kernel(const float* __restrict__ W,
                             const float* __restrict__ bias) {
    __shared__ float red[1024];
    int b = blockIdx.x;
    int c = threadIdx.x;  // 0..767
    if (c < 256) red[768 + c] = 0.f;  // zero-pad to 1024 for the tree

    float s = 0.f;
#pragma unroll
    for (int z = 0; z < NCHUNK; z++)
        s += g_part[((size_t)z * Bn + b) * Cn + c];
    float p = s * (1.0f / 1024.0f);

    float acc[4];
#pragma unroll
    for (int k = 0; k < 4; k++)
        acc[k] = p * W[k * Cn + c];

#pragma unroll
    for (int k = 0; k < 4; k++) {
        __syncthreads();
        red[c] = acc[k];
        __syncthreads();
        for (int st = 512; st > 0; st >>= 1) {
            if (c < st) red[c] += red[c + st];
            __syncthreads();
        }
        if (c == 0) g_alpha[b * 4 + k] = red[0] + bias[k];
    }
}

// Pass 3: paired merge. Rows l and 1023-l share the same 4 source rows:
//   {l, t(l), 1023-l, 1023-t(l)},  t(l) = (l%32)*32 + l/32, t(1023-l)=1023-t(l)
// One block = one (b, l<512) pair; 192 threads, float4 (768 floats/row).
__global__ void merge_kernel(const float* __restrict__ x,
                             float* __restrict__ out) {
    int bid = blockIdx.x;
    int b  = bid >> 9;        // /512
    int l  = bid & 511;
    int i  = l >> 5, j = l & 31;
    int tl  = (j << 5) | i;
    int rl  = 1023 - l;
    int rtl = 1023 - tl;

    float a0 = g_alpha[b * 4 + 0];
    float a1 = g_alpha[b * 4 + 1];
    float a2 = g_alpha[b * 4 + 2];
    float a3 = g_alpha[b * 4 + 3];

    const float4* xb = (const float4*)(x + (size_t)b * Nn * Cn);
    float4*       ob = (float4*)(out + (size_t)b * Nn * Cn);
    int t = threadIdx.x;  // 0..191 (192 float4 = 768 floats per row)

    float4 v0 = xb[(size_t)l   * 192 + t];
    float4 v1 = xb[(size_t)tl  * 192 + t];
    float4 v2 = xb[(size_t)rl  * 192 + t];
    float4 v3 = xb[(size_t)rtl * 192 + t];

    float4 o, r;
    o.x = a0 * v0.x + a1 * v1.x + a2 * v2.x + a3 * v3.x;
    o.y = a0 * v0.y + a1 * v1.y + a2 * v2.y + a3 * v3.y;
    o.z = a0 * v0.z + a1 * v1.z + a2 * v2.z + a3 * v3.z;
    o.w = a0 * v0.w + a1 * v1.w + a2 * v2.w + a3 * v3.w;
    // out row rl uses the same rows with roles swapped: {rl, rtl, l, tl}
    r.x = a0 * v2.x + a1 * v3.x + a2 * v0.x + a3 * v1.x;
    r.y = a0 * v2.y + a1 * v3.y + a2 * v0.y + a3 * v1.y;
    r.z = a0 * v2.z + a1 * v3.z + a2 * v0.z + a3 * v1.z;
    r.w = a0 * v2.w + a1 * v3.w + a2 * v0.w + a3 * v1.w;

    ob[(size_t)l  * 192 + t] = o;
    ob[(size_t)rl * 192 + t] = r;
}

extern "C" void kernel_launch(void* const* d_in, const int* in_sizes, int n_in,
                              void* d_out, int out_size) {
    const float* x    = (const float*)d_in[0];  // (32,1024,768)
    const float* W    = (const float*)d_in[1];  // (4,768)
    const float* bias = (const float*)d_in[2];  // (4,)
    float* out = (float*)d_out;

    dim3 g1(Bn, 3, NCHUNK);
    pool_partial_kernel<<<g1, 256>>>(x);
    alpha_kernel<<<Bn, Cn>>>(W, bias);
    merge_kernel<<<Bn * 512, 192>>>(x, out);
}

// round 2
// speedup vs baseline: 1.1028x; 1.1028x over previous
#include <cuda_runtime.h>

#define Bn 32
#define Nn 1024
#define Cn 768
#define C4 192        // Cn / 4
#define ZCHUNK 32
#define ROWS_PER_Z 32 // Nn / ZCHUNK

// Scratch (no allocation allowed in kernel_launch)
__device__ float4 g_part4[ZCHUNK * Bn * C4];  // partial channel sums (float4)
__device__ float  g_alpha[Bn * 4];            // per-batch merge coefficients

// Pass 1: partial channel sums, float4 wide.
// grid (Bn, ZCHUNK), block 192. Thread owns one float4 column for 32 rows.
__global__ void pool_partial_kernel(const float* __restrict__ x) {
    int b = blockIdx.x;
    int z = blockIdx.y;
    int t = threadIdx.x;  // 0..191
    const float4* p = (const float4*)(x + ((size_t)b * Nn + (size_t)z * ROWS_PER_Z) * Cn) + t;

    float4 s0 = {0,0,0,0}, s1 = {0,0,0,0}, s2 = {0,0,0,0}, s3 = {0,0,0,0};
#pragma unroll
    for (int n = 0; n < ROWS_PER_Z; n += 4) {
        float4 v0 = p[(size_t)(n + 0) * C4];
        float4 v1 = p[(size_t)(n + 1) * C4];
        float4 v2 = p[(size_t)(n + 2) * C4];
        float4 v3 = p[(size_t)(n + 3) * C4];
        s0.x += v0.x; s0.y += v0.y; s0.z += v0.z; s0.w += v0.w;
        s1.x += v1.x; s1.y += v1.y; s1.z += v1.z; s1.w += v1.w;
        s2.x += v2.x; s2.y += v2.y; s2.z += v2.z; s2.w += v2.w;
        s3.x += v3.x; s3.y += v3.y; s3.z += v3.z; s3.w += v3.w;
    }
    float4 s;
    s.x = (s0.x + s1.x) + (s2.x + s3.x);
    s.y = (s0.y + s1.y) + (s2.y + s3.y);
    s.z = (s0.z + s1.z) + (s2.z + s3.z);
    s.w = (s0.w + s1.w) + (s2.w + s3.w);
    g_part4[((size_t)z * Bn + b) * C4 + t] = s;
}

// Pass 2: alpha[b,k] = (1/1024) * sum_c (sum_z part[z,b,c]) * W[k,c] + bias[k]
// grid (Bn), block 768. Deterministic shared-memory tree reduction.
__global__ void alpha_kernel(const float* __restrict__ W,
                             const float* __restrict__ bias) {
    __shared__ float red[1024];
    int b = blockIdx.x;
    int c = threadIdx.x;  // 0..767
    if (c < 256) red[768 + c] = 0.f;

    const float* part = (const float*)g_part4;  // layout [z][b][768]
    float s = 0.f;
#pragma unroll
    for (int z = 0; z < ZCHUNK; z++)
        s += part[((size_t)z * Bn + b) * Cn + c];
    float p = s * (1.0f / 1024.0f);

    float acc[4];
#pragma unroll
    for (int k = 0; k < 4; k++)
        acc[k] = p * W[k * Cn + c];

#pragma unroll
    for (int k = 0; k < 4; k++) {
        __syncthreads();
        red[c] = acc[k];
        __syncthreads();
        for (int st = 512; st > 0; st >>= 1) {
            if (c < st) red[c] += red[c + st];
            __syncthreads();
        }
        if (c == 0) g_alpha[b * 4 + k] = red[0] + bias[k];
    }
}

// Pass 3: orbit merge. Under {id, transpose t, reverse r, rt} rows form orbits
//   {l, tl, rl, rtl}, tl = (l%32)*32 + l/32, rl = 1023-l, rtl = 1023-tl.
// Orbit representatives: l = 32i+j with i <= j <= 31-i  (272 orbits).
// One block reads the 4 rows ONCE and writes all 4 output rows:
//   out[m] = a0*x[m] + a1*x[t(m)] + a2*x[r(m)] + a3*x[rt(m)]
// which for the orbit members is a fixed permutation of (v0,v1,v2,v3).
// Degenerate orbits (tl==l or rl==tl) produce duplicate writes of identical
// values from the same thread — deterministic and correct.
__global__ void merge_kernel(const float* __restrict__ x,
                             float* __restrict__ out) {
    int bid = blockIdx.x;
    int b = bid / 272;
    int o = bid % 272;
    // decode orbit index -> (i, j): for row i there are 32-2i reps
    int i = 0;
    int cnt = 32;
    while (o >= cnt) { o -= cnt; i++; cnt -= 2; }
    int j = i + o;

    int l   = (i << 5) | j;
    int tl  = (j << 5) | i;
    int rl  = 1023 - l;
    int rtl = 1023 - tl;

    float a0 = g_alpha[b * 4 + 0];
    float a1 = g_alpha[b * 4 + 1];
    float a2 = g_alpha[b * 4 + 2];
    float a3 = g_alpha[b * 4 + 3];

    const float4* xb = (const float4*)(x + (size_t)b * Nn * Cn);
    float4*       ob = (float4*)(out + (size_t)b * Nn * Cn);
    int t = threadIdx.x;  // 0..191

    float4 v0 = xb[(size_t)l   * C4 + t];
    float4 v1 = xb[(size_t)tl  * C4 + t];
    float4 v2 = xb[(size_t)rl  * C4 + t];
    float4 v3 = xb[(size_t)rtl * C4 + t];

    float4 w;
    // out[l] = a0 v0 + a1 v1 + a2 v2 + a3 v3
    w.x = fmaf(a0, v0.x, fmaf(a1, v1.x, fmaf(a2, v2.x, a3 * v3.x)));
    w.y = fmaf(a0, v0.y, fmaf(a1, v1.y, fmaf(a2, v2.y, a3 * v3.y)));
    w.z = fmaf(a0, v0.z, fmaf(a1, v1.z, fmaf(a2, v2.z, a3 * v3.z)));
    w.w = fmaf(a0, v0.w, fmaf(a1, v1.w, fmaf(a2, v2.w, a3 * v3.w)));
    __stcs(&ob[(size_t)l * C4 + t], w);

    // out[tl] = a0 v1 + a1 v0 + a2 v3 + a3 v2
    w.x = fmaf(a0, v1.x, fmaf(a1, v0.x, fmaf(a2, v3.x, a3 * v2.x)));
    w.y = fmaf(a0, v1.y, fmaf(a1, v0.y, fmaf(a2, v3.y, a3 * v2.y)));
    w.z = fmaf(a0, v1.z, fmaf(a1, v0.z, fmaf(a2, v3.z, a3 * v2.z)));
    w.w = fmaf(a0, v1.w, fmaf(a1, v0.w, fmaf(a2, v3.w, a3 * v2.w)));
    __stcs(&ob[(size_t)tl * C4 + t], w);

    // out[rl] = a0 v2 + a1 v3 + a2 v0 + a3 v1
    w.x = fmaf(a0, v2.x, fmaf(a1, v3.x, fmaf(a2, v0.x, a3 * v1.x)));
    w.y = fmaf(a0, v2.y, fmaf(a1, v3.y, fmaf(a2, v0.y, a3 * v1.y)));
    w.z = fmaf(a0, v2.z, fmaf(a1, v3.z, fmaf(a2, v0.z, a3 * v1.z)));
    w.w = fmaf(a0, v2.w, fmaf(a1, v3.w, fmaf(a2, v0.w, a3 * v1.w)));
    __stcs(&ob[(size_t)rl * C4 + t], w);

    // out[rtl] = a0 v3 + a1 v2 + a2 v1 + a3 v0
    w.x = fmaf(a0, v3.x, fmaf(a1, v2.x, fmaf(a2, v1.x, a3 * v0.x)));
    w.y = fmaf(a0, v3.y, fmaf(a1, v2.y, fmaf(a2, v1.y, a3 * v0.y)));
    w.z = fmaf(a0, v3.z, fmaf(a1, v2.z, fmaf(a2, v1.z, a3 * v0.z)));
    w.w = fmaf(a0, v3.w, fmaf(a1, v2.w, fmaf(a2, v1.w, a3 * v0.w)));
    __stcs(&ob[(size_t)rtl * C4 + t], w);
}

extern "C" void kernel_launch(void* const* d_in, const int* in_sizes, int n_in,
                              void* d_out, int out_size) {
    const float* x    = (const float*)d_in[0];  // (32,1024,768)
    const float* W    = (const float*)d_in[1];  // (4,768)
    const float* bias = (const float*)d_in[2];  // (4,)
    float* out = (float*)d_out;

    dim3 g1(Bn, ZCHUNK);
    pool_partial_kernel<<<g1, C4>>>(x);
    alpha_kernel<<<Bn, Cn>>>(W, bias);
    merge_kernel<<<Bn * 272, C4>>>(x, out);
}

// round 3
// speedup vs baseline: 1.1516x; 1.0442x over previous
#include <cuda_runtime.h>

#define Bn 32
#define Nn 1024
#define Cn 768
#define C4 192        // Cn / 4
#define ZCHUNK 32
#define ROWS_PER_Z 32 // Nn / ZCHUNK

// Scratch (no allocation allowed in kernel_launch)
__device__ float4 g_part4[Bn * ZCHUNK * C4];  // partial channel sums, [b][z][c4]
__device__ float  g_alpha[Bn * 4];            // per-batch merge coefficients

// Pass 1: partial channel sums, float4 wide, MLP=8 per thread.
// grid (Bn, ZCHUNK), block 192. Thread owns one float4 column for 32 rows.
__global__ void pool_partial_kernel(const float* __restrict__ x) {
    int b = blockIdx.x;
    int z = blockIdx.y;
    int t = threadIdx.x;  // 0..191
    const float4* p = (const float4*)(x + ((size_t)b * Nn + (size_t)z * ROWS_PER_Z) * Cn) + t;

    float4 a0 = {0,0,0,0}, a1 = {0,0,0,0}, a2 = {0,0,0,0}, a3 = {0,0,0,0};
#pragma unroll
    for (int n = 0; n < ROWS_PER_Z; n += 8) {
        float4 v[8];
#pragma unroll
        for (int u = 0; u < 8; u++)
            v[u] = p[(size_t)(n + u) * C4];
        a0.x += v[0].x + v[4].x; a0.y += v[0].y + v[4].y;
        a0.z += v[0].z + v[4].z; a0.w += v[0].w + v[4].w;
        a1.x += v[1].x + v[5].x; a1.y += v[1].y + v[5].y;
        a1.z += v[1].z + v[5].z; a1.w += v[1].w + v[5].w;
        a2.x += v[2].x + v[6].x; a2.y += v[2].y + v[6].y;
        a2.z += v[2].z + v[6].z; a2.w += v[2].w + v[6].w;
        a3.x += v[3].x + v[7].x; a3.y += v[3].y + v[7].y;
        a3.z += v[3].z + v[7].z; a3.w += v[3].w + v[7].w;
    }
    float4 s;
    s.x = (a0.x + a1.x) + (a2.x + a3.x);
    s.y = (a0.y + a1.y) + (a2.y + a3.y);
    s.z = (a0.z + a1.z) + (a2.z + a3.z);
    s.w = (a0.w + a1.w) + (a2.w + a3.w);
    g_part4[((size_t)b * ZCHUNK + z) * C4 + t] = s;
}

// Pass 2: alpha[b,k] = (1/1024) * sum_c (sum_z part[b,z,c]) * W[k,c] + bias[k]
// grid (Bn), block 768 (24 warps). Warp-shuffle reduction, one barrier.
__global__ void alpha_kernel(const float* __restrict__ W,
                             const float* __restrict__ bias) {
    __shared__ float wsum[24][4];
    int b = blockIdx.x;
    int c = threadIdx.x;          // 0..767
    int lane = c & 31, wid = c >> 5;

    const float* part = (const float*)g_part4;  // [b][z][768]
    float s = 0.f;
#pragma unroll
    for (int z = 0; z < ZCHUNK; z++)
        s += part[((size_t)b * ZCHUNK + z) * Cn + c];
    float p = s * (1.0f / 1024.0f);

    float acc[4];
#pragma unroll
    for (int k = 0; k < 4; k++)
        acc[k] = p * W[k * Cn + c];

#pragma unroll
    for (int k = 0; k < 4; k++) {
#pragma unroll
        for (int off = 16; off > 0; off >>= 1)
            acc[k] += __shfl_down_sync(0xffffffffu, acc[k], off);
        if (lane == 0) wsum[wid][k] = acc[k];
    }
    __syncthreads();

    if (threadIdx.x < 128) {  // 4 warps, one per k
        int k = threadIdx.x >> 5;
        int l = threadIdx.x & 31;
        float v = (l < 24) ? wsum[l][k] : 0.f;
#pragma unroll
        for (int off = 16; off > 0; off >>= 1)
            v += __shfl_down_sync(0xffffffffu, v, off);
        if (l == 0) g_alpha[b * 4 + k] = v + bias[k];
    }
}

// Pass 3: orbit merge. Under {id, transpose t, reverse r, rt} rows form orbits
//   {l, tl, rl, rtl}, tl = (l%32)*32 + l/32, rl = 1023-l, rtl = 1023-tl.
// Orbit representatives: l = 32i+j with i <= j <= 31-i  (272 orbits).
// One block reads the 4 rows ONCE and writes all 4 output rows.
__global__ void merge_kernel(const float* __restrict__ x,
                             float* __restrict__ out) {
    int bid = blockIdx.x;
    int b = bid / 272;
    int o = bid % 272;
    int i = 0;
    int cnt = 32;
    while (o >= cnt) { o -= cnt; i++; cnt -= 2; }
    int j = i + o;

    int l   = (i << 5) | j;
    int tl  = (j << 5) | i;
    int rl  = 1023 - l;
    int rtl = 1023 - tl;

    float a0 = g_alpha[b * 4 + 0];
    float a1 = g_alpha[b * 4 + 1];
    float a2 = g_alpha[b * 4 + 2];
    float a3 = g_alpha[b * 4 + 3];

    const float4* xb = (const float4*)(x + (size_t)b * Nn * Cn);
    float4*       ob = (float4*)(out + (size_t)b * Nn * Cn);
    int t = threadIdx.x;  // 0..191

    float4 v0 = xb[(size_t)l   * C4 + t];
    float4 v1 = xb[(size_t)tl  * C4 + t];
    float4 v2 = xb[(size_t)rl  * C4 + t];
    float4 v3 = xb[(size_t)rtl * C4 + t];

    float4 w;
    // out[l] = a0 v0 + a1 v1 + a2 v2 + a3 v3
    w.x = fmaf(a0, v0.x, fmaf(a1, v1.x, fmaf(a2, v2.x, a3 * v3.x)));
    w.y = fmaf(a0, v0.y, fmaf(a1, v1.y, fmaf(a2, v2.y, a3 * v3.y)));
    w.z = fmaf(a0, v0.z, fmaf(a1, v1.z, fmaf(a2, v2.z, a3 * v3.z)));
    w.w = fmaf(a0, v0.w, fmaf(a1, v1.w, fmaf(a2, v2.w, a3 * v3.w)));
    __stcs(&ob[(size_t)l * C4 + t], w);

    // out[tl] = a0 v1 + a1 v0 + a2 v3 + a3 v2
    w.x = fmaf(a0, v1.x, fmaf(a1, v0.x, fmaf(a2, v3.x, a3 * v2.x)));
    w.y = fmaf(a0, v1.y, fmaf(a1, v0.y, fmaf(a2, v3.y, a3 * v2.y)));
    w.z = fmaf(a0, v1.z, fmaf(a1, v0.z, fmaf(a2, v3.z, a3 * v2.z)));
    w.w = fmaf(a0, v1.w, fmaf(a1, v0.w, fmaf(a2, v3.w, a3 * v2.w)));
    __stcs(&ob[(size_t)tl * C4 + t], w);

    // out[rl] = a0 v2 + a1 v3 + a2 v0 + a3 v1
    w.x = fmaf(a0, v2.x, fmaf(a1, v3.x, fmaf(a2, v0.x, a3 * v1.x)));
    w.y = fmaf(a0, v2.y, fmaf(a1, v3.y, fmaf(a2, v0.y, a3 * v1.y)));
    w.z = fmaf(a0, v2.z, fmaf(a1, v3.z, fmaf(a2, v0.z, a3 * v1.z)));
    w.w = fmaf(a0, v2.w, fmaf(a1, v3.w, fmaf(a2, v0.w, a3 * v1.w)));
    __stcs(&ob[(size_t)rl * C4 + t], w);

    // out[rtl] = a0 v3 + a1 v2 + a2 v1 + a3 v0
    w.x = fmaf(a0, v3.x, fmaf(a1, v2.x, fmaf(a2, v1.x, a3 * v0.x)));
    w.y = fmaf(a0, v3.y, fmaf(a1, v2.y, fmaf(a2, v1.y, a3 * v0.y)));
    w.z = fmaf(a0, v3.z, fmaf(a1, v2.z, fmaf(a2, v1.z, a3 * v0.z)));
    w.w = fmaf(a0, v3.w, fmaf(a1, v2.w, fmaf(a2, v1.w, a3 * v0.w)));
    __stcs(&ob[(size_t)rtl * C4 + t], w);
}

extern "C" void kernel_launch(void* const* d_in, const int* in_sizes, int n_in,
                              void* d_out, int out_size) {
    const float* x    = (const float*)d_in[0];  // (32,1024,768)
    const float* W    = (const float*)d_in[1];  // (4,768)
    const float* bias = (const float*)d_in[2];  // (4,)
    float* out = (float*)d_out;

    dim3 g1(Bn, ZCHUNK);
    pool_partial_kernel<<<g1, C4>>>(x);
    alpha_kernel<<<Bn, Cn>>>(W, bias);
    merge_kernel<<<Bn * 272, C4>>>(x, out);
}